// round 10
// baseline (speedup 1.0000x reference)
#include <cuda_runtime.h>
#include <cstdint>

// Problem constants
#define HID   1024
#define INP   128
#define NBAT  32
#define LSTEP 2048
#define KTOT  1152            // 1024 (h) + 128 (x)
#define COLS  64              // hidden columns per CTA (lane covers 2)
#define ROWSB 4               // batch rows per CTA
#define NCOLB 16              // column blocks (= CTAs per group)
#define NBATB 8               // batch groups
#define GRID  (NCOLB * NBATB) // 128 CTAs (single wave)
#define NTHR  512
#define NWARP 16
#define KW    72              // k per warp
#define NCH   18              // chunks of 4k
#define NWF   36              // f32x2 W regs (col0)

// Per-CTA epoch flags: g_flags[g][c] = number of steps CTA (g,c) has
// published. Single writer per slot; monotonic across launches/replays.
// All slots of a group are equal at launch entry (prior launch drained).
__device__ unsigned g_flags[NBATB][NCOLB];

__device__ __forceinline__ unsigned long long fma2(unsigned long long a,
                                                   unsigned long long b,
                                                   unsigned long long c) {
    unsigned long long d;
    asm("fma.rn.f32x2 %0, %1, %2, %3;" : "=l"(d) : "l"(a), "l"(b), "l"(c));
    return d;
}

__device__ __forceinline__ unsigned long long pack2(float x, float y) {
    unsigned long long r;
    asm("mov.b64 %0, {%1, %2};" : "=l"(r) : "f"(x), "f"(y));
    return r;
}

__device__ __forceinline__ float unpack_sum(unsigned long long v) {
    float lo, hi;
    asm("mov.b64 {%0, %1}, %2;" : "=f"(lo), "=f"(hi) : "l"(v));
    return lo + hi;
}

// smem layout (floats):
//   Ws   [288][32][4]     : 36864  (col1 W; [w*NCH+ch][lane][4k])
//   HP   [ROWSB][KTOT]    :  4608  ([h(t-1) | x_t] per row)
//   part [ROWSB][COLS][17]:  4352  (conflict-free reduce scratch)
//   bias [COLS]           :    64
#define SM_WS  0
#define SM_HP  (288 * 32 * 4)
#define SM_P   (SM_HP + ROWSB * KTOT)
#define PSTR   17
#define SM_B   (SM_P + ROWSB * COLS * PSTR)
#define SM_TOT (SM_B + COLS)            // 45888 floats = 183552 bytes

__global__ void __launch_bounds__(NTHR, 1)
reservoir_persistent(const float* __restrict__ input,   // (L, N, I)
                     const float* __restrict__ h_init,  // (N, H)
                     const float* __restrict__ W_in,    // (H, I)
                     const float* __restrict__ bias,    // (H)
                     const float* __restrict__ W_h,     // (H, H)
                     float* __restrict__ out)           // (L, N, H)
{
    extern __shared__ float smem[];
    float* Ws     = smem + SM_WS;
    float* HP     = smem + SM_HP;
    float* part_s = smem + SM_P;
    float* bias_s = smem + SM_B;

    const int tid = threadIdx.x;
    const int bx  = blockIdx.x;
    const int c   = bx & (NCOLB - 1);   // column block id (0..15)
    const int g   = bx >> 4;            // batch group id (0..7)
    const int j0  = c * COLS;
    const int n0  = g * ROWSB;

    // Epoch base: our OWN slot (single-writer -> race-free read).
    const unsigned base = *(volatile unsigned*)&g_flags[g][c];

    const int w    = tid >> 5;          // warp = k-slice (72 k)
    const int lane = tid & 31;
    const int k0   = w * KW;
    const int col0 = j0 + lane;         // W in registers
    // col1 = j0 + 32 + lane            // W in shared

    // ---- One-time: W col0 into regs (f32x2 packed; k0 & 1024 both even) ----
    unsigned long long w0[NWF];
    #pragma unroll
    for (int i = 0; i < NWF; ++i) {
        int k = k0 + 2 * i;
        float2 v;
        if (k < HID) v = *(const float2*)(W_h + (size_t)col0 * HID + k);
        else         v = *(const float2*)(W_in + (size_t)col0 * INP + (k - HID));
        w0[i] = pack2(v.x, v.y);
    }
    // ---- One-time: W col1 into shared: Ws[cg][l][kk] ----
    for (int i = tid; i < 288 * 32 * 4; i += NTHR) {
        int kk = i & 3;
        int l  = (i >> 2) & 31;
        int cg = i >> 7;
        int k  = 4 * cg + kk;
        int cl = j0 + 32 + l;
        float v = (k < HID) ? W_h[(size_t)cl * HID + k]
                            : W_in[(size_t)cl * INP + (k - HID)];
        Ws[i] = v;
    }
    if (tid < COLS) bias_s[tid] = bias[j0 + tid];
    __syncthreads();

    const ulonglong2* wsp = (const ulonglong2*)Ws + (size_t)(w * NCH) * 32 + lane;
    const int rn = tid >> 6;            // reduce row (0..3), first 256 thr
    const int rj = tid & 63;            // reduce col (0..63)

    for (int t = 0; t < LSTEP; ++t) {
        // ---- A: reduce step t-1 (16 partials + bias + tanh) and publish ----
        if (t > 0) {
            if (tid < 256) {
                float s = bias_s[rj];
                #pragma unroll
                for (int ww = 0; ww < NWARP; ++ww)
                    s += part_s[(rn * COLS + rj) * PSTR + ww];
                float hv = tanhf(s);
                out[((size_t)(t - 1) * NBAT + n0 + rn) * HID + j0 + rj] = hv;
            }
            // B: make reduce STGs block-visible before the release store
            __syncthreads();

            // C: release our h(t-1); concurrently detect peers' (single hop)
            if (tid == 0) {
                __threadfence();   // release: out[t-1] visible before flag
                *(volatile unsigned*)&g_flags[g][c] = base + (unsigned)t;
            }
            if (tid == NTHR - 1) {
                const unsigned target = base + (unsigned)t;
                for (;;) {
                    bool ok = true;
                    #pragma unroll
                    for (int i = 0; i < NCOLB; ++i) {
                        if (i == c) continue;
                        unsigned v = *(volatile unsigned*)&g_flags[g][i];
                        if ((int)(v - target) < 0) { ok = false; break; }
                    }
                    if (ok) break;
                }
                __threadfence();   // acquire
            }
            // D: fan out "all peers published h(t-1)" to the whole CTA
            __syncthreads();
        }

        // ---- E: stage h(t-1) and x(t) into HP ----
        const float* hsrc = (t == 0) ? (h_init + (size_t)n0 * HID)
                                     : (out + ((size_t)(t - 1) * NBAT + n0) * HID);
        #pragma unroll
        for (int rep = 0; rep < 2; ++rep) {
            int i = tid + rep * NTHR;   // 0..1023 -> 4 rows x 256 f4
            int n = i >> 8, q = i & 255;
            float4 v = ((const float4*)(hsrc + (size_t)n * HID))[q];
            *(float4*)(HP + n * KTOT + 4 * q) = v;
        }
        if (tid < 128) {
            int n = tid >> 5, q = tid & 31;
            float4 xv = ((const float4*)(input +
                         ((size_t)t * NBAT + n0 + n) * INP))[q];
            *(float4*)(HP + n * KTOT + HID + 4 * q) = xv;
        }
        __syncthreads();   // F

        // ---- G: compute (R6 verbatim): h broadcast LDS, W reg + smem ----
        const char* ab = (const char*)HP + (size_t)k0 * 4;
        unsigned long long acc[2 * ROWSB];
        #pragma unroll
        for (int i = 0; i < 2 * ROWSB; ++i) acc[i] = 0ull;

        #pragma unroll
        for (int ch = 0; ch < NCH; ++ch) {
            ulonglong2 wv = wsp[ch * 32];
            #pragma unroll
            for (int r = 0; r < ROWSB; ++r) {
                ulonglong2 a = *(const ulonglong2*)(ab + r * (KTOT * 4) + 16 * ch);
                acc[2 * r]     = fma2(a.x, w0[2 * ch],     acc[2 * r]);
                acc[2 * r]     = fma2(a.y, w0[2 * ch + 1], acc[2 * r]);
                acc[2 * r + 1] = fma2(a.x, wv.x,           acc[2 * r + 1]);
                acc[2 * r + 1] = fma2(a.y, wv.y,           acc[2 * r + 1]);
            }
        }

        // ---- H: dump partials: part[r][col][w], stride-17 conflict-free ----
        #pragma unroll
        for (int r = 0; r < ROWSB; ++r) {
            part_s[(r * COLS + lane) * PSTR + w]      = unpack_sum(acc[2 * r]);
            part_s[(r * COLS + 32 + lane) * PSTR + w] = unpack_sum(acc[2 * r + 1]);
        }
        __syncthreads();   // I: part_s complete for next iteration's reduce
    }

    // ---- Final: reduce step LSTEP-1 (no flag needed; kernel exit) ----
    if (tid < 256) {
        float s = bias_s[rj];
        #pragma unroll
        for (int ww = 0; ww < NWARP; ++ww)
            s += part_s[(rn * COLS + rj) * PSTR + ww];
        float hv = tanhf(s);
        out[((size_t)(LSTEP - 1) * NBAT + n0 + rn) * HID + j0 + rj] = hv;
    }
}

extern "C" void kernel_launch(void* const* d_in, const int* in_sizes, int n_in,
                              void* d_out, int out_size) {
    (void)in_sizes; (void)n_in; (void)out_size;
    const float* input  = (const float*)d_in[0];  // (2048, 32, 128)
    const float* h_init = (const float*)d_in[1];  // (32, 1024)
    const float* W_in   = (const float*)d_in[2];  // (1024, 128)
    const float* bias   = (const float*)d_in[3];  // (1024)
    const float* W_h    = (const float*)d_in[4];  // (1024, 1024)
    float* out = (float*)d_out;                   // (2048, 32, 1024)

    cudaFuncSetAttribute(reservoir_persistent,
                         cudaFuncAttributeMaxDynamicSharedMemorySize,
                         SM_TOT * (int)sizeof(float));
    reservoir_persistent<<<GRID, NTHR, SM_TOT * sizeof(float)>>>(
        input, h_init, W_in, bias, W_h, out);
}

// round 11
// speedup vs baseline: 1.6614x; 1.6614x over previous
#include <cuda_runtime.h>
#include <cstdint>

// Problem constants
#define HID   1024
#define INP   128
#define NBAT  32
#define LSTEP 2048
#define KTOT  1152            // 1024 (h) + 128 (x)
#define COLS  64              // hidden columns per CTA (lane covers 2)
#define ROWSB 4               // batch rows per CTA
#define NCOLB 16              // column blocks (= CTAs per group)
#define NBATB 8               // batch groups
#define GRID  (NCOLB * NBATB) // 128 CTAs (single wave)
#define NTHR  512
#define NWARP 16
#define KW    72              // k per warp
#define NCH   18              // chunks of 4k
#define NWF   36              // f32x2 W regs (col0)

// Per-CTA epoch flags. One 64B-aligned sector per group (16 x u32), padded to
// 128B so groups don't share lines. Single writer per slot; monotonic across
// launches/replays (wrap-safe compares).
__device__ __align__(128) unsigned g_flags[NBATB][32];

__device__ __forceinline__ unsigned long long fma2(unsigned long long a,
                                                   unsigned long long b,
                                                   unsigned long long c) {
    unsigned long long d;
    asm("fma.rn.f32x2 %0, %1, %2, %3;" : "=l"(d) : "l"(a), "l"(b), "l"(c));
    return d;
}

__device__ __forceinline__ unsigned long long pack2(float x, float y) {
    unsigned long long r;
    asm("mov.b64 %0, {%1, %2};" : "=l"(r) : "f"(x), "f"(y));
    return r;
}

__device__ __forceinline__ float unpack_sum(unsigned long long v) {
    float lo, hi;
    asm("mov.b64 {%0, %1}, %2;" : "=f"(lo), "=f"(hi) : "l"(v));
    return lo + hi;
}

// smem layout (floats):
//   Ws   [288][32][4]     : 36864  (col1 W; [w*NCH+ch][lane][4k])
//   HP   [ROWSB][KTOT]    :  4608  ([h(t-1) | x_t] per row)
//   part [ROWSB][COLS][17]:  4352  (conflict-free reduce scratch)
//   bias [COLS]           :    64
#define SM_WS  0
#define SM_HP  (288 * 32 * 4)
#define SM_P   (SM_HP + ROWSB * KTOT)
#define PSTR   17
#define SM_B   (SM_P + ROWSB * COLS * PSTR)
#define SM_TOT (SM_B + COLS)            // 45888 floats = 183552 bytes

__global__ void __launch_bounds__(NTHR, 1)
reservoir_persistent(const float* __restrict__ input,   // (L, N, I)
                     const float* __restrict__ h_init,  // (N, H)
                     const float* __restrict__ W_in,    // (H, I)
                     const float* __restrict__ bias,    // (H)
                     const float* __restrict__ W_h,     // (H, H)
                     float* __restrict__ out)           // (L, N, H)
{
    extern __shared__ float smem[];
    float* Ws     = smem + SM_WS;
    float* HP     = smem + SM_HP;
    float* part_s = smem + SM_P;
    float* bias_s = smem + SM_B;

    const int tid = threadIdx.x;
    const int bx  = blockIdx.x;
    const int c   = bx & (NCOLB - 1);   // column block id (0..15)
    const int g   = bx >> 4;            // batch group id (0..7)
    const int j0  = c * COLS;
    const int n0  = g * ROWSB;

    // Epoch base: our OWN slot (single-writer -> race-free read; all slots of
    // a group are equal at launch entry because the prior launch drained).
    const unsigned base = *(volatile unsigned*)&g_flags[g][c];

    const int w    = tid >> 5;          // warp = k-slice (72 k)
    const int lane = tid & 31;
    const int k0   = w * KW;
    const int col0 = j0 + lane;         // W in registers
    // col1 = j0 + 32 + lane            // W in shared

    // ---- One-time: W col0 into regs (f32x2 packed; k0 & 1024 both even) ----
    unsigned long long w0[NWF];
    #pragma unroll
    for (int i = 0; i < NWF; ++i) {
        int k = k0 + 2 * i;
        float2 v;
        if (k < HID) v = *(const float2*)(W_h + (size_t)col0 * HID + k);
        else         v = *(const float2*)(W_in + (size_t)col0 * INP + (k - HID));
        w0[i] = pack2(v.x, v.y);
    }
    // ---- One-time: W col1 into shared: Ws[cg][l][kk] ----
    for (int i = tid; i < 288 * 32 * 4; i += NTHR) {
        int kk = i & 3;
        int l  = (i >> 2) & 31;
        int cg = i >> 7;
        int k  = 4 * cg + kk;
        int cl = j0 + 32 + l;
        float v = (k < HID) ? W_h[(size_t)cl * HID + k]
                            : W_in[(size_t)cl * INP + (k - HID)];
        Ws[i] = v;
    }
    if (tid < COLS) bias_s[tid] = bias[j0 + tid];
    __syncthreads();

    const ulonglong2* wsp = (const ulonglong2*)Ws + (size_t)(w * NCH) * 32 + lane;
    const int rn = tid >> 6;            // reduce row (0..3), first 256 thr
    const int rj = tid & 63;            // reduce col (0..63)

    for (int t = 0; t < LSTEP; ++t) {
        // ---- A: reduce step t-1 (16 partials + bias + tanh) ----
        if (t > 0) {
            if (tid < 256) {
                float s = bias_s[rj];
                #pragma unroll
                for (int ww = 0; ww < NWARP; ++ww)
                    s += part_s[(rn * COLS + rj) * PSTR + ww];
                float hv = tanhf(s);
                out[((size_t)(t - 1) * NBAT + n0 + rn) * HID + j0 + rj] = hv;
            }
            // B: make reduce STGs block-wide complete before the release
            __syncthreads();

            // C: release our h(t-1) (one store; peers detect in one hop)
            if (tid == 0) {
                __threadfence();   // release: out[t-1] visible before flag
                *(volatile unsigned*)&g_flags[g][c] = base + (unsigned)t;
            }

            // X: stage x(t) now — independent of peers; HP is dead here
            // (every thread passed bars I and B since HP was last read).
            if (tid < 128) {
                int n = tid >> 5, q = tid & 31;
                float4 xv = ((const float4*)(input +
                             ((size_t)t * NBAT + n0 + n) * INP))[q];
                *(float4*)(HP + n * KTOT + HID + 4 * q) = xv;
            }

            // P: PARALLEL detection by warp 15 (idle in reduce): lane i
            // watches flag i; all 16 flags live in one 64B sector -> each
            // retry costs ONE L2 round trip. Exit requires all lanes'
            // observations true in the SAME iteration (collective verify),
            // then bar D fans out. (Unlike R2/R3: no thread proceeds on a
            // partial condition.)
            if (tid >= NTHR - 32) {
                const unsigned target = base + (unsigned)t;
                volatile unsigned* fp = &g_flags[g][lane & (NCOLB - 1)];
                for (;;) {
                    unsigned v = *fp;
                    bool ok = (int)(v - target) >= 0;
                    if (__all_sync(0xFFFFFFFFu, ok)) break;
                }
                __threadfence();   // acquire
            }
            // D: fan out "all peers published h(t-1)"
            __syncthreads();
        } else {
            // t == 0: stage x(0)
            if (tid < 128) {
                int n = tid >> 5, q = tid & 31;
                float4 xv = ((const float4*)(input + (size_t)(n0 + n) * INP))[q];
                *(float4*)(HP + n * KTOT + HID + 4 * q) = xv;
            }
        }

        // ---- E: stage h(t-1) into HP ----
        const float* hsrc = (t == 0) ? (h_init + (size_t)n0 * HID)
                                     : (out + ((size_t)(t - 1) * NBAT + n0) * HID);
        #pragma unroll
        for (int rep = 0; rep < 2; ++rep) {
            int i = tid + rep * NTHR;   // 0..1023 -> 4 rows x 256 f4
            int n = i >> 8, q = i & 255;
            float4 v = ((const float4*)(hsrc + (size_t)n * HID))[q];
            *(float4*)(HP + n * KTOT + 4 * q) = v;
        }
        __syncthreads();   // F

        // ---- G: compute (R6 verbatim): h broadcast LDS, W reg + smem ----
        const char* ab = (const char*)HP + (size_t)k0 * 4;
        unsigned long long acc[2 * ROWSB];
        #pragma unroll
        for (int i = 0; i < 2 * ROWSB; ++i) acc[i] = 0ull;

        #pragma unroll
        for (int ch = 0; ch < NCH; ++ch) {
            ulonglong2 wv = wsp[ch * 32];
            #pragma unroll
            for (int r = 0; r < ROWSB; ++r) {
                ulonglong2 a = *(const ulonglong2*)(ab + r * (KTOT * 4) + 16 * ch);
                acc[2 * r]     = fma2(a.x, w0[2 * ch],     acc[2 * r]);
                acc[2 * r]     = fma2(a.y, w0[2 * ch + 1], acc[2 * r]);
                acc[2 * r + 1] = fma2(a.x, wv.x,           acc[2 * r + 1]);
                acc[2 * r + 1] = fma2(a.y, wv.y,           acc[2 * r + 1]);
            }
        }

        // ---- H: dump partials: part[r][col][w], stride-17 conflict-free ----
        #pragma unroll
        for (int r = 0; r < ROWSB; ++r) {
            part_s[(r * COLS + lane) * PSTR + w]      = unpack_sum(acc[2 * r]);
            part_s[(r * COLS + 32 + lane) * PSTR + w] = unpack_sum(acc[2 * r + 1]);
        }
        __syncthreads();   // I: part_s complete for next iteration's reduce
    }

    // ---- Final: reduce step LSTEP-1 (no flag; kernel exit) ----
    if (tid < 256) {
        float s = bias_s[rj];
        #pragma unroll
        for (int ww = 0; ww < NWARP; ++ww)
            s += part_s[(rn * COLS + rj) * PSTR + ww];
        float hv = tanhf(s);
        out[((size_t)(LSTEP - 1) * NBAT + n0 + rn) * HID + j0 + rj] = hv;
    }
}

extern "C" void kernel_launch(void* const* d_in, const int* in_sizes, int n_in,
                              void* d_out, int out_size) {
    (void)in_sizes; (void)n_in; (void)out_size;
    const float* input  = (const float*)d_in[0];  // (2048, 32, 128)
    const float* h_init = (const float*)d_in[1];  // (32, 1024)
    const float* W_in   = (const float*)d_in[2];  // (1024, 128)
    const float* bias   = (const float*)d_in[3];  // (1024)
    const float* W_h    = (const float*)d_in[4];  // (1024, 1024)
    float* out = (float*)d_out;                   // (2048, 32, 1024)

    cudaFuncSetAttribute(reservoir_persistent,
                         cudaFuncAttributeMaxDynamicSharedMemorySize,
                         SM_TOT * (int)sizeof(float));
    reservoir_persistent<<<GRID, NTHR, SM_TOT * sizeof(float)>>>(
        input, h_init, W_in, bias, W_h, out);
}